// round 9
// baseline (speedup 1.0000x reference)
#include <cuda_runtime.h>
#include <cuda_fp16.h>

#define DFT 784
#define DP  800              // padded feature dim (zero-padded tail)
#define PAD 64               // over-allocation so prefetch needs no guard
#define KC  50
#define LF  6
#define NB  2
#define THREADS 128
#define NWARPS (THREADS/32)
#define NITER 25             // DP/32
#define STW 30
#define NCAND 4              // exact-rescore candidates per sample

typedef unsigned long long u64;

// Exact fp32 tables (rescore path): c_i = sqrt(invD)*a_i, s=sqrt(invD), nsmu=-s*mu
__device__ __align__(16) float4 g_C0[KC * DP + PAD];   // {c0,c1,c2,c3}
__device__ __align__(16) float4 g_C1[KC * DP + PAD];   // {c4,c5,s,nsmu}
__device__ float g_LD[KC * DP + PAD];
// fp16 hot-loop tables: g_Hc = {h2(c0,c1),h2(c2,c3),h2(c4,c5),h2(s,nsmu)}, g_Hld = h2(ld,ld)
__device__ __align__(16) uint4 g_Hc[KC * DP + PAD];
__device__ unsigned g_Hld[KC * DP + PAD];

__device__ __forceinline__ constexpr int IJ(int i, int j) { return i * (i + 1) / 2 + j; }

// ---- f32x2 helpers (for flush + reduction only) ----
__device__ __forceinline__ u64 pk2(float a, float b) {
    u64 r; asm("mov.b64 %0,{%1,%2};" : "=l"(r) : "f"(a), "f"(b)); return r;
}
__device__ __forceinline__ void upk2(u64 v, float& a, float& b) {
    asm("mov.b64 {%0,%1},%2;" : "=f"(a), "=f"(b) : "l"(v));
}
__device__ __forceinline__ u64 add2(u64 a, u64 b) {
    u64 d; asm("add.rn.f32x2 %0,%1,%2;" : "=l"(d) : "l"(a), "l"(b)); return d;
}
__device__ __forceinline__ __half2 bch2(unsigned u) {
    return *reinterpret_cast<__half2*>(&u);
}

__global__ void pack_kernel(const float* __restrict__ A_fac,
                            const float* __restrict__ MU,
                            const float* __restrict__ log_D)
{
    int idx = blockIdx.x * blockDim.x + threadIdx.x;
    if (idx >= KC * DP + PAD) return;
    int k = idx / DP, d = idx - k * DP;
    if (k < KC && d < DFT) {
        int src = k * DFT + d;
        const float* a = A_fac + (size_t)src * LF;
        float ld = log_D[src];
        float s  = expf(-0.5f * ld);
        float c0 = s*a[0], c1 = s*a[1], c2 = s*a[2], c3 = s*a[3], c4 = s*a[4], c5 = s*a[5];
        float nsmu = -s * MU[src];
        g_C0[idx] = make_float4(c0, c1, c2, c3);
        g_C1[idx] = make_float4(c4, c5, s, nsmu);
        g_LD[idx] = ld;
        __half2 h01 = __floats2half2_rn(c0, c1);
        __half2 h23 = __floats2half2_rn(c2, c3);
        __half2 h45 = __floats2half2_rn(c4, c5);
        __half2 hsn = __floats2half2_rn(s, nsmu);
        uint4 hv;
        hv.x = *reinterpret_cast<unsigned*>(&h01);
        hv.y = *reinterpret_cast<unsigned*>(&h23);
        hv.z = *reinterpret_cast<unsigned*>(&h45);
        hv.w = *reinterpret_cast<unsigned*>(&hsn);
        g_Hc[idx] = hv;
        __half2 hld = __floats2half2_rn(ld, ld);
        g_Hld[idx] = *reinterpret_cast<unsigned*>(&hld);
    } else {
        g_C0[idx] = make_float4(0.f, 0.f, 0.f, 0.f);
        g_C1[idx] = make_float4(0.f, 0.f, 0.f, 0.f);
        g_LD[idx] = 0.f;
        g_Hc[idx] = make_uint4(0u, 0u, 0u, 0u);
        g_Hld[idx] = 0u;
    }
}

__device__ __forceinline__ float chol6(float* S, float* inv)
{
    float prod = 1.f;
    #pragma unroll
    for (int j = 0; j < LF; j++) {
        float s = S[IJ(j, j)];
        #pragma unroll
        for (int m = 0; m < j; m++) s = fmaf(-S[IJ(j, m)], S[IJ(j, m)], s);
        prod *= s;
        float rs = rsqrtf(s);
        inv[j] = rs;
        S[IJ(j, j)] = s * rs;
        #pragma unroll
        for (int i = j + 1; i < LF; i++) {
            float t = S[IJ(i, j)];
            #pragma unroll
            for (int m = 0; m < j; m++) t = fmaf(-S[IJ(i, m)], S[IJ(j, m)], t);
            S[IJ(i, j)] = t * rs;
        }
    }
    return prod;
}

__device__ __forceinline__ float fwd6(const float* L, const float* inv, const float* q, float* y)
{
    float ysq = 0.f;
    #pragma unroll
    for (int i = 0; i < LF; i++) {
        float t = q[i];
        #pragma unroll
        for (int m = 0; m < i; m++) t = fmaf(-L[IJ(i, m)], y[m], t);
        y[i] = t * inv[i];
        ysq = fmaf(y[i], y[i], ysq);
    }
    return ysq;
}

// fp16x2 accumulate step: halves = 2 samples. in = {jf_h2 (lo32), xj_h2 (hi32)}.
__device__ __forceinline__ void consume_h(uint4 cv, unsigned ldu, u64 in, __half2* acc)
{
    __half2 jf2 = bch2((unsigned)(in & 0xffffffffu));
    __half2 xj2 = bch2((unsigned)(in >> 32));
    __half2 c01 = bch2(cv.x), c23 = bch2(cv.y), c45 = bch2(cv.z), sns = bch2(cv.w);
    __half2 ld2 = bch2(ldu);
    __half2 sb  = __low2half2(sns);
    __half2 nsb = __high2half2(sns);
    __half2 cb[LF] = { __low2half2(c01), __high2half2(c01),
                       __low2half2(c23), __high2half2(c23),
                       __low2half2(c45), __high2half2(c45) };

    __half2 e2 = __hfma2(nsb, jf2, __hmul2(sb, xj2));   // sqrt(invD)*masked residual
    acc[27] = __hfma2(e2, e2, acc[27]);                 // quad
    acc[28] = __hfma2(jf2, ld2, acc[28]);               // Jf . logD

    #pragma unroll
    for (int i = 0; i < LF; i++) {
        acc[21 + i] = __hfma2(e2, cb[i], acc[21 + i]);  // q
        __half2 ja = __hmul2(jf2, cb[i]);
        #pragma unroll
        for (int j = 0; j <= i; j++)
            acc[IJ(i, j)] = __hfma2(ja, cb[j], acc[IJ(i, j)]);  // P
    }
}

__global__ __launch_bounds__(THREADS, 4)
void mfa_main(const float* __restrict__ X, const int* __restrict__ J,
              const float* __restrict__ MU, const float* __restrict__ A_fac,
              const float* __restrict__ log_D, const float* __restrict__ PI,
              float* __restrict__ outPw, float* __restrict__ outM,
              float* __restrict__ outA, float* __restrict__ outD)
{
    __shared__ u64    s_in8[DP + PAD];         // {jf_h2, xj_h2}
    __shared__ float2 s_xj[DP + PAD];          // exact {xj0, xj1} for rescore
    __shared__ float  s_pi[KC];
    __shared__ float  s_stats[KC][NB][STW];    // approx raw sums
    __shared__ float  s_score[KC * NB];
    __shared__ int    s_cand[NB][NCAND];
    __shared__ float  s_exsc[NB * NCAND];
    __shared__ float  s_exPq[NB * NCAND][27];
    __shared__ float  s_mz[NB][LF];
    __shared__ float  s_Lzm[NB][21];
    __shared__ int    s_c[NB];

    const int tid  = threadIdx.x;
    const int lane = tid & 31;
    const int warp = tid >> 5;
    const int b0   = blockIdx.x * NB;

    for (int t = tid; t < DP + PAD; t += THREADS) {
        if (t < DFT) {
            float x0  = X[(size_t)b0 * DFT + t];
            float x1  = X[(size_t)(b0 + 1) * DFT + t];
            bool  j0  = (J[(size_t)b0 * DFT + t] == 1);
            bool  j1  = (J[(size_t)(b0 + 1) * DFT + t] == 1);
            float jf0 = j0 ? 1.0f : 0.0f, jf1 = j1 ? 1.0f : 0.0f;
            float xj0 = j0 ? x0 : 0.0f,   xj1 = j1 ? x1 : 0.0f;
            __half2 hjf = __floats2half2_rn(jf0, jf1);
            __half2 hxj = __floats2half2_rn(xj0, xj1);
            s_in8[t] = (u64)(*reinterpret_cast<unsigned*>(&hjf))
                     | ((u64)(*reinterpret_cast<unsigned*>(&hxj)) << 32);
            s_xj[t] = make_float2(xj0, xj1);
        } else {
            s_in8[t] = 0ull;
            s_xj[t] = make_float2(0.f, 0.f);
        }
    }
    for (int t = tid; t < KC; t += THREADS) s_pi[t] = PI[t];
    __syncthreads();

    const __half2 hzero = __floats2half2_rn(0.f, 0.f);

    // ---- Phase 1 (fp16x2 accumulate, fp32 flush every 8-9 d) ----
    for (int k = warp; k < KC; k += NWARPS) {
        __half2 acch[29];
        u64 accf[29];
        #pragma unroll
        for (int t = 0; t < 29; t++) { acch[t] = hzero; accf[t] = 0ull; }

        const uint4*    __restrict__ ph  = g_Hc  + (size_t)k * DP;
        const unsigned* __restrict__ pld = g_Hld + (size_t)k * DP;

        uint4 sl[2]; unsigned sld[2];
        sl[0] = ph[lane];       sld[0] = pld[lane];
        sl[1] = ph[lane + 32];  sld[1] = pld[lane + 32];

        int t = 0;
        #pragma unroll
        for (int c = 0; c < 3; c++) {
            const int CH = (c == 2) ? 9 : 8;
            #pragma unroll
            for (int i = 0; i < CH; i++) {
                uint4 cur = sl[t & 1]; unsigned curld = sld[t & 1];
                int dn = lane + 32 * (t + 2);      // always in-bounds via PAD
                sl[t & 1] = ph[dn]; sld[t & 1] = pld[dn];
                consume_h(cur, curld, s_in8[lane + 32 * t], acch);
                t++;
            }
            // flush fp16 partials into packed fp32
            #pragma unroll
            for (int u = 0; u < 29; u++) {
                float2 f = __half22float2(acch[u]);
                accf[u] = add2(accf[u], pk2(f.x, f.y));
                acch[u] = hzero;
            }
        }

        // Split-sample reduction on packed fp32, then fp32 butterflies.
        const bool odd = (lane & 1);
        float r[29];
        #pragma unroll
        for (int u = 0; u < 29; u++) {
            u64 o = __shfl_xor_sync(0xffffffffu, accf[u], 1);
            float slo, shi, olo, ohi;
            upk2(accf[u], slo, shi);
            upk2(o, olo, ohi);
            r[u] = odd ? (shi + ohi) : (slo + olo);
        }
        #pragma unroll
        for (int u = 0; u < 29; u++) {
            #pragma unroll
            for (int off = 2; off < 32; off <<= 1)
                r[u] += __shfl_xor_sync(0xffffffffu, r[u], off);
        }
        if (lane < 2) {
            #pragma unroll
            for (int u = 0; u < 29; u++) s_stats[k][lane][u] = r[u];
        }
    }
    __syncthreads();

    // ---- Phase 1.5: block-parallel approximate scoring ----
    if (tid < KC * NB) {
        const int k  = tid >> 1;
        const int b2 = tid & 1;
        float P[21], q[LF];
        #pragma unroll
        for (int u = 0; u < 21; u++) P[u] = s_stats[k][b2][u];
        float quad = s_stats[k][b2][27];
        float jld  = s_stats[k][b2][28];
        #pragma unroll
        for (int i = 0; i < LF; i++) { P[IJ(i, i)] += 1.0f; q[i] = s_stats[k][b2][21 + i]; }
        float inv[LF];
        float prod = chol6(P, inv);
        float y[LF];
        float ysq = fwd6(P, inv, q, y);
        s_score[tid] = s_pi[k] - 0.5f * (quad - ysq + __logf(prod) + jld);
    }
    __syncthreads();

    // ---- Phase 2a: approx top-NCAND per sample ----
    if (tid < NB) {
        const int b2 = tid;
        float ts[NCAND]; int tk[NCAND];
        #pragma unroll
        for (int c = 0; c < NCAND; c++) { ts[c] = -1e30f; tk[c] = 0; }
        for (int k = 0; k < KC; k++) {
            float sc = s_score[k * NB + b2];
            if (sc > ts[NCAND - 1]) {
                int p = NCAND - 1;
                while (p > 0 && sc > ts[p - 1]) { ts[p] = ts[p-1]; tk[p] = tk[p-1]; p--; }
                ts[p] = sc; tk[p] = k;
            }
        }
        #pragma unroll
        for (int c = 0; c < NCAND; c++) s_cand[b2][c] = tk[c];
    }
    __syncthreads();

    // ---- Phase 2b: exact fp32 rescore of candidates (one warp per task) ----
    for (int task = warp; task < NB * NCAND; task += NWARPS) {
        const int b2 = task % NB;
        const int cd = task / NB;
        const int k  = s_cand[b2][cd];
        const float4* __restrict__ p0 = g_C0 + (size_t)k * DP;
        const float4* __restrict__ p1 = g_C1 + (size_t)k * DP;
        const float*  __restrict__ pl = g_LD + (size_t)k * DP;

        float a[29];
        #pragma unroll
        for (int u = 0; u < 29; u++) a[u] = 0.f;

        for (int d = lane; d < DP; d += 32) {
            float4 v0 = p0[d], v1 = p1[d];
            float ldv = pl[d];
            float2 xj = s_xj[d];
            float2 jfv = __half22float2(bch2((unsigned)(s_in8[d] & 0xffffffffu)));
            float jf  = b2 ? jfv.y : jfv.x;
            float xjb = b2 ? xj.y  : xj.x;
            float c[LF] = {v0.x, v0.y, v0.z, v0.w, v1.x, v1.y};
            float e = fmaf(v1.w, jf, v1.z * xjb);
            a[27] = fmaf(e, e, a[27]);
            a[28] = fmaf(jf, ldv, a[28]);
            #pragma unroll
            for (int i = 0; i < LF; i++) {
                a[21 + i] = fmaf(e, c[i], a[21 + i]);
                float jc = jf * c[i];
                #pragma unroll
                for (int j = 0; j <= i; j++)
                    a[IJ(i, j)] = fmaf(jc, c[j], a[IJ(i, j)]);
            }
        }
        #pragma unroll
        for (int u = 0; u < 29; u++) {
            float v = a[u];
            #pragma unroll
            for (int off = 16; off > 0; off >>= 1)
                v += __shfl_xor_sync(0xffffffffu, v, off);
            a[u] = v;
        }
        if (lane == 0) {
            float P[21], q[LF];
            #pragma unroll
            for (int u = 0; u < 21; u++) P[u] = a[u];
            #pragma unroll
            for (int i = 0; i < LF; i++) { P[IJ(i, i)] += 1.0f; q[i] = a[21 + i]; }
            float inv[LF];
            float prod = chol6(P, inv);
            float y[LF];
            float ysq = fwd6(P, inv, q, y);
            s_exsc[task] = s_pi[k] - 0.5f * (a[27] - ysq + __logf(prod) + a[28]);
            #pragma unroll
            for (int u = 0; u < 21; u++) s_exPq[task][u] = a[u];
            #pragma unroll
            for (int i = 0; i < LF; i++) s_exPq[task][21 + i] = a[21 + i];
        }
    }
    __syncthreads();

    // ---- Phase 2c: pick exact winner, small linalg ----
    if (tid < NB) {
        const int b2 = tid;
        int wc = 0; float best = -1e30f;
        for (int cdd = 0; cdd < NCAND; cdd++) {
            float sc = s_exsc[cdd * NB + b2];
            if (sc > best) { best = sc; wc = cdd; }
        }
        const int task = wc * NB + b2;
        s_c[b2] = s_cand[b2][wc];

        float P[21], q[LF];
        #pragma unroll
        for (int u = 0; u < 21; u++) P[u] = s_exPq[task][u];
        #pragma unroll
        for (int i = 0; i < LF; i++) { P[IJ(i, i)] += 1.0f; q[i] = s_exPq[task][21 + i]; }

        float inv[LF];
        (void)chol6(P, inv);
        float y[LF];
        (void)fwd6(P, inv, q, y);
        float mz[LF];
        #pragma unroll
        for (int ii = LF - 1; ii >= 0; ii--) {
            float t = y[ii];
            #pragma unroll
            for (int m = ii + 1; m < LF; m++) t = fmaf(-P[IJ(m, ii)], mz[m], t);
            mz[ii] = t * inv[ii];
        }
        float Li[21];
        #pragma unroll
        for (int j = 0; j < LF; j++) {
            Li[IJ(j, j)] = inv[j];
            #pragma unroll
            for (int i = j + 1; i < LF; i++) {
                float t = 0.f;
                #pragma unroll
                for (int m = j; m < i; m++) t = fmaf(P[IJ(i, m)], Li[IJ(m, j)], t);
                Li[IJ(i, j)] = -inv[i] * t;
            }
        }
        float C[21];
        #pragma unroll
        for (int i = 0; i < LF; i++)
            #pragma unroll
            for (int j = 0; j <= i; j++) {
                float t = 0.f;
                #pragma unroll
                for (int m = i; m < LF; m++) t = fmaf(Li[IJ(m, i)], Li[IJ(m, j)], t);
                C[IJ(i, j)] = t;
            }
        float invz[LF];
        (void)chol6(C, invz);
        #pragma unroll
        for (int i = 0; i < LF; i++) s_mz[b2][i] = mz[i];
        #pragma unroll
        for (int u = 0; u < 21; u++) s_Lzm[b2][u] = C[u];
    }
    __syncthreads();

    // ---- Epilogue: stream outputs (exact original inputs) ----
    #pragma unroll
    for (int b2 = 0; b2 < NB; b2++) {
        const int b = b0 + b2;
        const int c = s_c[b2];
        float mz[LF], Lz[21];
        #pragma unroll
        for (int i = 0; i < LF; i++) mz[i] = s_mz[b2][i];
        #pragma unroll
        for (int u = 0; u < 21; u++) Lz[u] = s_Lzm[b2][u];
        const float* __restrict__ ac  = A_fac + (size_t)c * DFT * LF;
        const float* __restrict__ muc = MU    + (size_t)c * DFT;
        const float* __restrict__ ldc = log_D + (size_t)c * DFT;
        for (int d = tid; d < DFT; d += THREADS) {
            const float2* ar = reinterpret_cast<const float2*>(ac + (size_t)d * LF);
            float2 r0 = ar[0], r1 = ar[1], r2 = ar[2];
            float a[LF] = {r0.x, r0.y, r1.x, r1.y, r2.x, r2.y};
            float Mo = muc[d];
            #pragma unroll
            for (int i = 0; i < LF; i++) Mo = fmaf(a[i], mz[i], Mo);
            outM[(size_t)b * DFT + d] = Mo;
            float Ao[LF];
            #pragma unroll
            for (int j = 0; j < LF; j++) {
                float s = 0.f;
                #pragma unroll
                for (int i = j; i < LF; i++) s = fmaf(a[i], Lz[IJ(i, j)], s);
                Ao[j] = s;
            }
            float2* pA = reinterpret_cast<float2*>(outA + ((size_t)b * DFT + d) * LF);
            pA[0] = make_float2(Ao[0], Ao[1]);
            pA[1] = make_float2(Ao[2], Ao[3]);
            pA[2] = make_float2(Ao[4], Ao[5]);
            outD[(size_t)b * DFT + d] = expf(ldc[d]);
        }
    }
    if (tid < NB) outPw[b0 + tid] = 1.0f;
}

extern "C" void kernel_launch(void* const* d_in, const int* in_sizes, int n_in,
                              void* d_out, int out_size)
{
    const float* X      = (const float*)d_in[0];
    const int*   J      = (const int*)  d_in[1];
    const float* MU     = (const float*)d_in[2];
    const float* A_fac  = (const float*)d_in[3];
    const float* log_D  = (const float*)d_in[4];
    const float* PI     = (const float*)d_in[5];
    float* out = (float*)d_out;

    const int B = in_sizes[0] / DFT;     // 2048
    float* outPw = out;
    float* outM  = out + B;
    float* outA  = outM + (size_t)B * DFT;
    float* outD  = outA + (size_t)B * DFT * LF;

    pack_kernel<<<(KC * DP + PAD + 255) / 256, 256>>>(A_fac, MU, log_D);
    mfa_main<<<B / NB, THREADS>>>(X, J, MU, A_fac, log_D, PI, outPw, outM, outA, outD);
}